// round 14
// baseline (speedup 1.0000x reference)
#include <cuda_runtime.h>
#include <cuda_fp16.h>
#include <cstdint>

#define NN 100000
#define NE_CAP 1700000
#define NB_SCAN 98   /* ceil(100000/1024) */

// ---- scratch (device globals: allocation-free) ----
__device__ __align__(16) __half g_Z1[NN * 64];
__device__ __align__(16) __half g_Z2[NN * 64];
__device__ __align__(16) __half g_Wt012[64 * 128];  // (W0W1W2)^T fp16
__device__ float g_u1[64];                          // W2^T b1
__device__ float g_u2[64];                          // (W1W2)^T b0
__device__ float g_onorm[NN];
__device__ float g_inorm[NN];
__device__ float g_t1[NN];
__device__ float g_t2[NN];
__device__ int   g_cin[NN];
__device__ int   g_cout[NN];
__device__ int   g_ptr[NN + 1];
__device__ int   g_fill[NN];
__device__ int   g_csr[NE_CAP];
__device__ int   g_part[NB_SCAN];
__device__ int   g_ctr;

// ---------------- graph preprocessing (r9-proven scan CSR) ----------------
__global__ void k_degree(const int* __restrict__ src, const int* __restrict__ dst,
                         int* cout, int* cin, int E) {
    int i = blockIdx.x * blockDim.x + threadIdx.x;
    if (i == 0) g_ctr = 0;
    if (i < E) {
        atomicAdd(&cout[src[i]], 1);
        atomicAdd(&cin[dst[i]], 1);
    }
}

// fused: norms + per-block partial sums + (last block) exclusive scan
__global__ void __launch_bounds__(256) k_norm_scan(const int* __restrict__ cout,
                                                   const int* __restrict__ cin,
                                                   float* onorm, float* inorm,
                                                   int* part, int* ptr) {
    __shared__ int wsum[8];
    __shared__ int lastflag;
    int b = blockIdx.x, t = threadIdx.x;
    int lane = t & 31, w = t >> 5;
    int base = b * 1024 + t * 4;
    int s = 0;
#pragma unroll
    for (int j = 0; j < 4; j++) {
        int i = base + j;
        if (i < NN) {
            int ci = cin[i];
            s += ci;
            inorm[i] = rsqrtf((float)(ci + 1));
            onorm[i] = rsqrtf((float)(cout[i] + 1));
        }
    }
    int rs = s;
    for (int o = 16; o > 0; o >>= 1) rs += __shfl_down_sync(0xffffffffu, rs, o);
    if (lane == 0) wsum[w] = rs;
    __syncthreads();
    if (t == 0) {
        int tot = 0;
        for (int i = 0; i < 8; i++) tot += wsum[i];
        part[b] = tot;
        __threadfence();
        int done = atomicAdd(&g_ctr, 1);
        lastflag = (done == NB_SCAN - 1) ? 1 : 0;
    }
    __syncthreads();
    if (lastflag) {
        int v = (t < NB_SCAN) ? ((volatile int*)part)[t] : 0;
        int inc = v;
        for (int o = 1; o < 32; o <<= 1) {
            int u = __shfl_up_sync(0xffffffffu, inc, o);
            if (lane >= o) inc += u;
        }
        if (lane == 31) wsum[w] = inc;
        __syncthreads();
        if (t == 0) {
            int r = 0;
#pragma unroll
            for (int i = 0; i < 8; i++) { int x = wsum[i]; wsum[i] = r; r += x; }
        }
        __syncthreads();
        int excl = wsum[w] + inc - v;
        if (t < NB_SCAN) part[t] = excl;
        if (t == NB_SCAN - 1) ptr[NN] = excl + v;
    }
}

__global__ void k_scan_write(const int* __restrict__ cin, const int* __restrict__ part,
                             int* ptr, int* fill) {
    __shared__ int wexc[8];
    int b = blockIdx.x, t = threadIdx.x;
    int lane = t & 31, warp = t >> 5;
    int base = b * 1024 + t * 4;
    int v[4];
#pragma unroll
    for (int j = 0; j < 4; j++) { int i = base + j; v[j] = (i < NN) ? cin[i] : 0; }
    int s = v[0] + v[1] + v[2] + v[3];
    int inc = s;
    for (int o = 1; o < 32; o <<= 1) {
        int u = __shfl_up_sync(0xffffffffu, inc, o);
        if (lane >= o) inc += u;
    }
    if (lane == 31) wexc[warp] = inc;
    __syncthreads();
    if (warp == 0) {
        int w = (lane < 8) ? wexc[lane] : 0;
        int winc = w;
        for (int o = 1; o < 8; o <<= 1) {
            int u = __shfl_up_sync(0xffffffffu, winc, o);
            if (lane >= o) winc += u;
        }
        if (lane < 8) wexc[lane] = winc - w;
    }
    __syncthreads();
    int pos = part[b] + wexc[warp] + (inc - s);
#pragma unroll
    for (int j = 0; j < 4; j++) {
        int i = base + j;
        if (i < NN) { ptr[i] = pos; fill[i] = pos; }
        pos += v[j];
    }
}

__global__ void k_fill(const int* __restrict__ src, const int* __restrict__ dst,
                       int* fill, int* csr, int E) {
    int i = blockIdx.x * blockDim.x + threadIdx.x;
    if (i < E) {
        int p = atomicAdd(&fill[dst[i]], 1);
        csr[p] = src[i];
    }
}

// ---------------- rank-1 bias helpers: t1 = S.1, t2 = S.t1 (scalar gathers) ----------------
__global__ void k_t1(const int* __restrict__ ptr, const int* __restrict__ csr,
                     const float* __restrict__ onorm, const float* __restrict__ inorm,
                     float* __restrict__ t1) {
    int v = blockIdx.x * blockDim.x + threadIdx.x;
    if (v >= NN) return;
    int beg = ptr[v], end = ptr[v + 1];
    float s = onorm[v];
    for (int e = beg; e < end; e++) s += onorm[csr[e]];
    t1[v] = inorm[v] * s;
}

__global__ void k_t2(const int* __restrict__ ptr, const int* __restrict__ csr,
                     const float* __restrict__ onorm, const float* __restrict__ inorm,
                     const float* __restrict__ t1, float* __restrict__ t2) {
    int v = blockIdx.x * blockDim.x + threadIdx.x;
    if (v >= NN) return;
    int beg = ptr[v], end = ptr[v + 1];
    float s = onorm[v] * t1[v];
    for (int e = beg; e < end; e++) { int u = csr[e]; s += onorm[u] * t1[u]; }
    t2[v] = inorm[v] * s;
}

// ---------------- combine weights: Wt012 = (W0 W1 W2)^T fp16; u1, u2 ----------------
__global__ void __launch_bounds__(256) k_wcomb(const float* __restrict__ W0,
                                               const float* __restrict__ W1,
                                               const float* __restrict__ W2,
                                               const float* __restrict__ b0,
                                               const float* __restrict__ b1,
                                               __half* __restrict__ Wt012,
                                               float* __restrict__ u1,
                                               float* __restrict__ u2) {
    __shared__ float T[64 * 64];          // W1 @ W2
    int t = threadIdx.x;
    // T[i][j] = sum_k W1[i][k] * W2[k][j]
    for (int idx = t; idx < 64 * 64; idx += 256) {
        int i = idx >> 6, j = idx & 63;
        float s = 0.f;
        for (int k = 0; k < 64; k++) s += W1[i * 64 + k] * W2[k * 64 + j];
        T[idx] = s;
    }
    __syncthreads();
    // Wt012[n][k] = W012[k][n] = sum_m W0[k][m] * T[m][n]   (k<128, n<64)
    for (int idx = t; idx < 64 * 128; idx += 256) {
        int n = idx >> 7, k = idx & 127;
        float s = 0.f;
        for (int m = 0; m < 64; m++) s += W0[k * 64 + m] * T[m * 64 + n];
        Wt012[idx] = __float2half(s);
    }
    // u1[j] = sum_k b1[k] W2[k][j];  u2[j] = sum_k b0[k] T[k][j]
    if (t < 64) {
        float s1 = 0.f, s2 = 0.f;
        for (int k = 0; k < 64; k++) {
            s1 += b1[k] * W2[k * 64 + t];
            s2 += b0[k] * T[k * 64 + t];
        }
        u1[t] = s1;
        u2[t] = s2;
    }
}

// ---------------- GEMM0: Z = fp16(h fp32 @ W012), B-in-registers, unscaled ----------------
__global__ void __launch_bounds__(128) k_gemm0(const float* __restrict__ A,
                                               const __half* __restrict__ Wt,
                                               __half* __restrict__ Z) {
    const int K = 128;
    const int tid = threadIdx.x;
    const int warp = tid >> 5, lane = tid & 31;
    const int g = lane >> 2, t = lane & 3;

    uint2 Bf[8][2];
#pragma unroll
    for (int k0 = 0; k0 < 8; k0++)
#pragma unroll
        for (int nn = 0; nn < 2; nn++)
            Bf[k0][nn] = *reinterpret_cast<const uint2*>(
                Wt + (long)(warp * 16 + nn * 8 + g) * K + k0 * 16 + 4 * t);

    const int rowblk = blockIdx.x * 128;

#pragma unroll
    for (int m = 0; m < 8; m++) {
        const int r0 = rowblk + m * 16 + g;
        const int r1 = r0 + 8;
        const int r0c = r0 < NN ? r0 : NN - 1;
        const int r1c = r1 < NN ? r1 : NN - 1;

        float acc[2][4];
#pragma unroll
        for (int nn = 0; nn < 2; nn++)
#pragma unroll
            for (int j = 0; j < 4; j++) acc[nn][j] = 0.f;

#pragma unroll
        for (int k0 = 0; k0 < 8; k0++) {
            float4 fA = *reinterpret_cast<const float4*>(A + (long)r0c * K + 4 * t + k0 * 16);
            float4 fB = *reinterpret_cast<const float4*>(A + (long)r1c * K + 4 * t + k0 * 16);
            __half2 hA0 = __floats2half2_rn(fA.x, fA.y), hA1 = __floats2half2_rn(fA.z, fA.w);
            __half2 hB0 = __floats2half2_rn(fB.x, fB.y), hB1 = __floats2half2_rn(fB.z, fB.w);
            uint2 aA, aB;
            aA.x = *reinterpret_cast<unsigned int*>(&hA0);
            aA.y = *reinterpret_cast<unsigned int*>(&hA1);
            aB.x = *reinterpret_cast<unsigned int*>(&hB0);
            aB.y = *reinterpret_cast<unsigned int*>(&hB1);
#pragma unroll
            for (int nn = 0; nn < 2; nn++) {
                asm volatile(
                    "mma.sync.aligned.m16n8k16.row.col.f32.f16.f16.f32 "
                    "{%0,%1,%2,%3},{%4,%5,%6,%7},{%8,%9},{%0,%1,%2,%3};"
                    : "+f"(acc[nn][0]), "+f"(acc[nn][1]), "+f"(acc[nn][2]), "+f"(acc[nn][3])
                    : "r"(aA.x), "r"(aB.x), "r"(aA.y), "r"(aB.y),
                      "r"(Bf[k0][nn].x), "r"(Bf[k0][nn].y));
            }
        }
#pragma unroll
        for (int nn = 0; nn < 2; nn++) {
            int col = warp * 16 + nn * 8 + 2 * t;
            if (r0 < NN)
                *reinterpret_cast<__half2*>(Z + (long)r0 * 64 + col) =
                    __floats2half2_rn(acc[nn][0], acc[nn][1]);
            if (r1 < NN)
                *reinterpret_cast<__half2*>(Z + (long)r1 * 64 + col) =
                    __floats2half2_rn(acc[nn][2], acc[nn][3]);
        }
    }
}

// ---------------- SpMM gathers ----------------
// MODE 0: ONORM_EDGE gather, epilogue *(inorm*onorm), fp16 out   (stage 1)
// MODE 1: plain gather,      epilogue *(inorm*onorm), fp16 out   (stage 2)
// MODE 2: plain gather, epilogue *inorm + t2*u2 + t1*u1 + b2, fp32 out (final)
template <int MODE>
__global__ void __launch_bounds__(256) k_gather(const __half* __restrict__ Zh,
                                                const int* __restrict__ ptr,
                                                const int* __restrict__ csr,
                                                const float* __restrict__ onorm,
                                                const float* __restrict__ inorm,
                                                const float* __restrict__ t1,
                                                const float* __restrict__ t2,
                                                const float* __restrict__ u1,
                                                const float* __restrict__ u2,
                                                const float* __restrict__ b2,
                                                void* __restrict__ Hout) {
    int v = (blockIdx.x * blockDim.x + threadIdx.x) >> 5;
    int lane = threadIdx.x & 31;
    if (v >= NN) return;
    const __half2* Z = reinterpret_cast<const __half2*>(Zh) + lane;  // row stride 32

    int beg = ptr[v], end = ptr[v + 1];
    float2 f0 = __half22float2(Z[(long)v * 32]);
    float selfw = (MODE == 0) ? onorm[v] : 1.f;
    float acc0 = f0.x * selfw, acc1 = f0.y * selfw;

    int e = beg;
    for (; e + 4 <= end; e += 4) {
        int s0 = csr[e], s1 = csr[e + 1], s2 = csr[e + 2], s3 = csr[e + 3];
        float2 a = __half22float2(Z[(long)s0 * 32]);
        float2 b = __half22float2(Z[(long)s1 * 32]);
        float2 c = __half22float2(Z[(long)s2 * 32]);
        float2 d = __half22float2(Z[(long)s3 * 32]);
        if (MODE == 0) {
            float w0 = onorm[s0], w1 = onorm[s1], w2 = onorm[s2], w3 = onorm[s3];
            acc0 = fmaf(w0, a.x, fmaf(w1, b.x, fmaf(w2, c.x, fmaf(w3, d.x, acc0))));
            acc1 = fmaf(w0, a.y, fmaf(w1, b.y, fmaf(w2, c.y, fmaf(w3, d.y, acc1))));
        } else {
            acc0 += (a.x + b.x) + (c.x + d.x);
            acc1 += (a.y + b.y) + (c.y + d.y);
        }
    }
    for (; e < end; e++) {
        int s = csr[e];
        float2 a = __half22float2(Z[(long)s * 32]);
        float w = (MODE == 0) ? onorm[s] : 1.f;
        acc0 = fmaf(w, a.x, acc0);
        acc1 = fmaf(w, a.y, acc1);
    }

    if (MODE == 2) {
        float ni = inorm[v];
        float tv1 = t1[v], tv2 = t2[v];
        float2 uu1 = *reinterpret_cast<const float2*>(u1 + lane * 2);
        float2 uu2 = *reinterpret_cast<const float2*>(u2 + lane * 2);
        float2 bb = *reinterpret_cast<const float2*>(b2 + lane * 2);
        float o0 = ni * acc0 + tv2 * uu2.x + tv1 * uu1.x + bb.x;
        float o1 = ni * acc1 + tv2 * uu2.y + tv1 * uu1.y + bb.y;
        *reinterpret_cast<float2*>(reinterpret_cast<float*>(Hout) + (long)v * 64 + lane * 2) =
            make_float2(o0, o1);
    } else {
        float sc = inorm[v] * onorm[v];
        reinterpret_cast<__half2*>(Hout)[(long)v * 32 + lane] =
            __floats2half2_rn(acc0 * sc, acc1 * sc);
    }
}

__global__ void k_ids(const int* __restrict__ ids, float* out, int n) {
    int i = blockIdx.x * blockDim.x + threadIdx.x;
    if (i < n) out[NN * 64 + i] = (float)ids[i];
}

// ---------------- launch ----------------
extern "C" void kernel_launch(void* const* d_in, const int* in_sizes, int n_in,
                              void* d_out, int out_size) {
    const float* h   = (const float*)d_in[0];
    const int*   src = (const int*)d_in[1];
    const int*   dst = (const int*)d_in[2];
    const int*   ids = (const int*)d_in[3];
    const float* W0  = (const float*)d_in[4];
    const float* b0  = (const float*)d_in[5];
    const float* W1  = (const float*)d_in[6];
    const float* b1  = (const float*)d_in[7];
    const float* W2  = (const float*)d_in[8];
    const float* b2  = (const float*)d_in[9];
    float* out = (float*)d_out;
    int E = in_sizes[1];

    __half *pZ1, *pZ2, *pWt;
    float *pon, *pin, *pt1, *pt2, *pu1, *pu2;
    int *pcin, *pcout, *pptr, *pfill, *pcsr, *ppart;
    cudaGetSymbolAddress((void**)&pZ1, g_Z1);
    cudaGetSymbolAddress((void**)&pZ2, g_Z2);
    cudaGetSymbolAddress((void**)&pWt, g_Wt012);
    cudaGetSymbolAddress((void**)&pu1, g_u1);
    cudaGetSymbolAddress((void**)&pu2, g_u2);
    cudaGetSymbolAddress((void**)&pon, g_onorm);
    cudaGetSymbolAddress((void**)&pin, g_inorm);
    cudaGetSymbolAddress((void**)&pt1, g_t1);
    cudaGetSymbolAddress((void**)&pt2, g_t2);
    cudaGetSymbolAddress((void**)&pcin, g_cin);
    cudaGetSymbolAddress((void**)&pcout, g_cout);
    cudaGetSymbolAddress((void**)&pptr, g_ptr);
    cudaGetSymbolAddress((void**)&pfill, g_fill);
    cudaGetSymbolAddress((void**)&pcsr, g_csr);
    cudaGetSymbolAddress((void**)&ppart, g_part);

    static cudaStream_t s2 = nullptr;
    static cudaEvent_t ev_fork = nullptr, ev_join = nullptr;
    if (s2 == nullptr) {
        cudaStreamCreateWithFlags(&s2, cudaStreamNonBlocking);
        cudaEventCreateWithFlags(&ev_fork, cudaEventDisableTiming);
        cudaEventCreateWithFlags(&ev_join, cudaEventDisableTiming);
    }

    const int gblk = (NN + 127) / 128;
    const int wblk = (NN * 32 + 255) / 256;
    const int nblk = (NN + 255) / 256;
    const int eblk = (E + 255) / 256;

    // ---- fork: prep chain + t1/t2 + ids on s2; wcomb + GEMM0 on main ----
    cudaEventRecord(ev_fork, 0);
    cudaStreamWaitEvent(s2, ev_fork, 0);

    cudaMemsetAsync(pcin, 0, NN * sizeof(int), s2);
    cudaMemsetAsync(pcout, 0, NN * sizeof(int), s2);
    k_degree<<<eblk, 256, 0, s2>>>(src, dst, pcout, pcin, E);
    k_norm_scan<<<NB_SCAN, 256, 0, s2>>>(pcout, pcin, pon, pin, ppart, pptr);
    k_scan_write<<<NB_SCAN, 256, 0, s2>>>(pcin, ppart, pptr, pfill);
    k_fill<<<eblk, 256, 0, s2>>>(src, dst, pfill, pcsr, E);
    k_t1<<<nblk, 256, 0, s2>>>(pptr, pcsr, pon, pin, pt1);
    k_t2<<<nblk, 256, 0, s2>>>(pptr, pcsr, pon, pin, pt1, pt2);
    if (out_size > NN * 64) {
        int nid = out_size - NN * 64;
        if (nid > in_sizes[3]) nid = in_sizes[3];
        k_ids<<<(nid + 255) / 256, 256, 0, s2>>>(ids, out, nid);
    }
    cudaEventRecord(ev_join, s2);

    k_wcomb<<<1, 256>>>(W0, W1, W2, b0, b1, pWt, pu1, pu2);
    k_gemm0<<<gblk, 128>>>(h, pWt, pZ1);      // X = h @ W012 (unscaled)

    cudaStreamWaitEvent(0, ev_join, 0);       // join: CSR + norms + t1/t2 ready

    // ---- three back-to-back gathers (no GEMMs in between) ----
    k_gather<0><<<wblk, 256>>>(pZ1, pptr, pcsr, pon, pin, pt1, pt2, pu1, pu2, b2, pZ2);
    k_gather<1><<<wblk, 256>>>(pZ2, pptr, pcsr, pon, pin, pt1, pt2, pu1, pu2, b2, pZ1);
    k_gather<2><<<wblk, 256>>>(pZ1, pptr, pcsr, pon, pin, pt1, pt2, pu1, pu2, b2, out);
}

// round 15
// speedup vs baseline: 1.0211x; 1.0211x over previous
#include <cuda_runtime.h>
#include <cuda_fp16.h>
#include <cstdint>

#define NN 100000
#define NE_CAP 1700000
#define NB_SCAN 98   /* ceil(100000/1024) */

// ---- scratch (device globals: allocation-free) ----
__device__ __align__(16) __half g_Z1[NN * 64];
__device__ __align__(16) __half g_Z2[NN * 64];
__device__ __align__(16) __half g_Wt012[64 * 128];  // (W0W1W2)^T fp16
__device__ float g_u1[64];                          // W2^T b1
__device__ float g_u2[64];                          // (W1W2)^T b0
__device__ float g_onorm[NN];
__device__ float g_inorm[NN];
__device__ float g_w[NN];                           // inorm*onorm
__device__ float g_t1[NN];
__device__ float g_t2[NN];
__device__ int   g_cin[NN];
__device__ int   g_cout[NN];
__device__ int   g_ptr[NN + 1];
__device__ int   g_fill[NN];
__device__ int   g_csr[NE_CAP];
__device__ int   g_part[NB_SCAN];
__device__ int   g_ctr;

// ---------------- graph preprocessing (r9-proven scan CSR) ----------------
__global__ void k_degree(const int* __restrict__ src, const int* __restrict__ dst,
                         int* cout, int* cin, int E) {
    int i = blockIdx.x * blockDim.x + threadIdx.x;
    if (i == 0) g_ctr = 0;
    if (i < E) {
        atomicAdd(&cout[src[i]], 1);
        atomicAdd(&cin[dst[i]], 1);
    }
}

// fused: norms (+ combined weight w=inorm*onorm) + block partials + last-block scan
__global__ void __launch_bounds__(256) k_norm_scan(const int* __restrict__ cout,
                                                   const int* __restrict__ cin,
                                                   float* onorm, float* inorm, float* wprod,
                                                   int* part, int* ptr) {
    __shared__ int wsum[8];
    __shared__ int lastflag;
    int b = blockIdx.x, t = threadIdx.x;
    int lane = t & 31, w = t >> 5;
    int base = b * 1024 + t * 4;
    int s = 0;
#pragma unroll
    for (int j = 0; j < 4; j++) {
        int i = base + j;
        if (i < NN) {
            int ci = cin[i];
            s += ci;
            float in_ = rsqrtf((float)(ci + 1));
            float on_ = rsqrtf((float)(cout[i] + 1));
            inorm[i] = in_;
            onorm[i] = on_;
            wprod[i] = in_ * on_;
        }
    }
    int rs = s;
    for (int o = 16; o > 0; o >>= 1) rs += __shfl_down_sync(0xffffffffu, rs, o);
    if (lane == 0) wsum[w] = rs;
    __syncthreads();
    if (t == 0) {
        int tot = 0;
        for (int i = 0; i < 8; i++) tot += wsum[i];
        part[b] = tot;
        __threadfence();
        int done = atomicAdd(&g_ctr, 1);
        lastflag = (done == NB_SCAN - 1) ? 1 : 0;
    }
    __syncthreads();
    if (lastflag) {
        int v = (t < NB_SCAN) ? ((volatile int*)part)[t] : 0;
        int inc = v;
        for (int o = 1; o < 32; o <<= 1) {
            int u = __shfl_up_sync(0xffffffffu, inc, o);
            if (lane >= o) inc += u;
        }
        if (lane == 31) wsum[w] = inc;
        __syncthreads();
        if (t == 0) {
            int r = 0;
#pragma unroll
            for (int i = 0; i < 8; i++) { int x = wsum[i]; wsum[i] = r; r += x; }
        }
        __syncthreads();
        int excl = wsum[w] + inc - v;
        if (t < NB_SCAN) part[t] = excl;
        if (t == NB_SCAN - 1) ptr[NN] = excl + v;
    }
}

__global__ void k_scan_write(const int* __restrict__ cin, const int* __restrict__ part,
                             int* ptr, int* fill) {
    __shared__ int wexc[8];
    int b = blockIdx.x, t = threadIdx.x;
    int lane = t & 31, warp = t >> 5;
    int base = b * 1024 + t * 4;
    int v[4];
#pragma unroll
    for (int j = 0; j < 4; j++) { int i = base + j; v[j] = (i < NN) ? cin[i] : 0; }
    int s = v[0] + v[1] + v[2] + v[3];
    int inc = s;
    for (int o = 1; o < 32; o <<= 1) {
        int u = __shfl_up_sync(0xffffffffu, inc, o);
        if (lane >= o) inc += u;
    }
    if (lane == 31) wexc[warp] = inc;
    __syncthreads();
    if (warp == 0) {
        int w = (lane < 8) ? wexc[lane] : 0;
        int winc = w;
        for (int o = 1; o < 8; o <<= 1) {
            int u = __shfl_up_sync(0xffffffffu, winc, o);
            if (lane >= o) winc += u;
        }
        if (lane < 8) wexc[lane] = winc - w;
    }
    __syncthreads();
    int pos = part[b] + wexc[warp] + (inc - s);
#pragma unroll
    for (int j = 0; j < 4; j++) {
        int i = base + j;
        if (i < NN) { ptr[i] = pos; fill[i] = pos; }
        pos += v[j];
    }
}

__global__ void k_fill(const int* __restrict__ src, const int* __restrict__ dst,
                       int* fill, int* csr, int E) {
    int i = blockIdx.x * blockDim.x + threadIdx.x;
    if (i < E) {
        int p = atomicAdd(&fill[dst[i]], 1);
        csr[p] = src[i];
    }
}

// ---------------- rank-1 bias helpers: t1 = S.1, t2 = S.t1 (scalar gathers) ----------------
// Run on s2 CONCURRENT with gathers 0/1; only the final gather consumes them.
__global__ void k_t1(const int* __restrict__ ptr, const int* __restrict__ csr,
                     const float* __restrict__ onorm, const float* __restrict__ inorm,
                     float* __restrict__ t1) {
    int v = blockIdx.x * blockDim.x + threadIdx.x;
    if (v >= NN) return;
    int beg = ptr[v], end = ptr[v + 1];
    float s = onorm[v];
    for (int e = beg; e < end; e++) s += onorm[csr[e]];
    t1[v] = inorm[v] * s;
}

__global__ void k_t2(const int* __restrict__ ptr, const int* __restrict__ csr,
                     const float* __restrict__ onorm, const float* __restrict__ inorm,
                     const float* __restrict__ t1, float* __restrict__ t2) {
    int v = blockIdx.x * blockDim.x + threadIdx.x;
    if (v >= NN) return;
    int beg = ptr[v], end = ptr[v + 1];
    float s = onorm[v] * t1[v];
    for (int e = beg; e < end; e++) { int u = csr[e]; s += onorm[u] * t1[u]; }
    t2[v] = inorm[v] * s;
}

// ---------------- combine weights: Wt012 = (W0 W1 W2)^T fp16; u1, u2 ----------------
__global__ void __launch_bounds__(256) k_wcomb(const float* __restrict__ W0,
                                               const float* __restrict__ W1,
                                               const float* __restrict__ W2,
                                               const float* __restrict__ b0,
                                               const float* __restrict__ b1,
                                               __half* __restrict__ Wt012,
                                               float* __restrict__ u1,
                                               float* __restrict__ u2) {
    __shared__ float T[64 * 64];          // W1 @ W2
    int t = threadIdx.x;
    for (int idx = t; idx < 64 * 64; idx += 256) {
        int i = idx >> 6, j = idx & 63;
        float s = 0.f;
        for (int k = 0; k < 64; k++) s += W1[i * 64 + k] * W2[k * 64 + j];
        T[idx] = s;
    }
    __syncthreads();
    for (int idx = t; idx < 64 * 128; idx += 256) {
        int n = idx >> 7, k = idx & 127;
        float s = 0.f;
        for (int m = 0; m < 64; m++) s += W0[k * 64 + m] * T[m * 64 + n];
        Wt012[idx] = __float2half(s);
    }
    if (t < 64) {
        float s1 = 0.f, s2 = 0.f;
        for (int k = 0; k < 64; k++) {
            s1 += b1[k] * W2[k * 64 + t];
            s2 += b0[k] * T[k * 64 + t];
        }
        u1[t] = s1;
        u2[t] = s2;
    }
}

// ---------------- GEMM0: Z = fp16(h fp32 @ W012), B-in-registers, unscaled ----------------
__global__ void __launch_bounds__(128) k_gemm0(const float* __restrict__ A,
                                               const __half* __restrict__ Wt,
                                               __half* __restrict__ Z) {
    const int K = 128;
    const int tid = threadIdx.x;
    const int warp = tid >> 5, lane = tid & 31;
    const int g = lane >> 2, t = lane & 3;

    uint2 Bf[8][2];
#pragma unroll
    for (int k0 = 0; k0 < 8; k0++)
#pragma unroll
        for (int nn = 0; nn < 2; nn++)
            Bf[k0][nn] = *reinterpret_cast<const uint2*>(
                Wt + (long)(warp * 16 + nn * 8 + g) * K + k0 * 16 + 4 * t);

    const int rowblk = blockIdx.x * 128;

#pragma unroll
    for (int m = 0; m < 8; m++) {
        const int r0 = rowblk + m * 16 + g;
        const int r1 = r0 + 8;
        const int r0c = r0 < NN ? r0 : NN - 1;
        const int r1c = r1 < NN ? r1 : NN - 1;

        float acc[2][4];
#pragma unroll
        for (int nn = 0; nn < 2; nn++)
#pragma unroll
            for (int j = 0; j < 4; j++) acc[nn][j] = 0.f;

#pragma unroll
        for (int k0 = 0; k0 < 8; k0++) {
            float4 fA = *reinterpret_cast<const float4*>(A + (long)r0c * K + 4 * t + k0 * 16);
            float4 fB = *reinterpret_cast<const float4*>(A + (long)r1c * K + 4 * t + k0 * 16);
            __half2 hA0 = __floats2half2_rn(fA.x, fA.y), hA1 = __floats2half2_rn(fA.z, fA.w);
            __half2 hB0 = __floats2half2_rn(fB.x, fB.y), hB1 = __floats2half2_rn(fB.z, fB.w);
            uint2 aA, aB;
            aA.x = *reinterpret_cast<unsigned int*>(&hA0);
            aA.y = *reinterpret_cast<unsigned int*>(&hA1);
            aB.x = *reinterpret_cast<unsigned int*>(&hB0);
            aB.y = *reinterpret_cast<unsigned int*>(&hB1);
#pragma unroll
            for (int nn = 0; nn < 2; nn++) {
                asm volatile(
                    "mma.sync.aligned.m16n8k16.row.col.f32.f16.f16.f32 "
                    "{%0,%1,%2,%3},{%4,%5,%6,%7},{%8,%9},{%0,%1,%2,%3};"
                    : "+f"(acc[nn][0]), "+f"(acc[nn][1]), "+f"(acc[nn][2]), "+f"(acc[nn][3])
                    : "r"(aA.x), "r"(aB.x), "r"(aA.y), "r"(aB.y),
                      "r"(Bf[k0][nn].x), "r"(Bf[k0][nn].y));
            }
        }
#pragma unroll
        for (int nn = 0; nn < 2; nn++) {
            int col = warp * 16 + nn * 8 + 2 * t;
            if (r0 < NN)
                *reinterpret_cast<__half2*>(Z + (long)r0 * 64 + col) =
                    __floats2half2_rn(acc[nn][0], acc[nn][1]);
            if (r1 < NN)
                *reinterpret_cast<__half2*>(Z + (long)r1 * 64 + col) =
                    __floats2half2_rn(acc[nn][2], acc[nn][3]);
        }
    }
}

// ---------------- SpMM gathers ----------------
// MODE 0: ONORM_EDGE gather, epilogue *w (=inorm*onorm), fp16 out   (stage 1)
// MODE 1: plain gather,      epilogue *w,                fp16 out   (stage 2)
// MODE 2: plain gather, epilogue *inorm + t2*u2 + t1*u1 + b2, fp32 out (final)
template <int MODE>
__global__ void __launch_bounds__(256) k_gather(const __half* __restrict__ Zh,
                                                const int* __restrict__ ptr,
                                                const int* __restrict__ csr,
                                                const float* __restrict__ onorm,
                                                const float* __restrict__ inorm,
                                                const float* __restrict__ wprod,
                                                const float* __restrict__ t1,
                                                const float* __restrict__ t2,
                                                const float* __restrict__ u1,
                                                const float* __restrict__ u2,
                                                const float* __restrict__ b2,
                                                void* __restrict__ Hout) {
    int v = (blockIdx.x * blockDim.x + threadIdx.x) >> 5;
    int lane = threadIdx.x & 31;
    if (v >= NN) return;
    const __half2* Z = reinterpret_cast<const __half2*>(Zh) + lane;  // row stride 32

    int beg = ptr[v], end = ptr[v + 1];
    float2 f0 = __half22float2(Z[(long)v * 32]);
    float selfw = (MODE == 0) ? onorm[v] : 1.f;
    float acc0 = f0.x * selfw, acc1 = f0.y * selfw;

    int e = beg;
    for (; e + 4 <= end; e += 4) {
        int s0 = csr[e], s1 = csr[e + 1], s2 = csr[e + 2], s3 = csr[e + 3];
        float2 a = __half22float2(Z[(long)s0 * 32]);
        float2 b = __half22float2(Z[(long)s1 * 32]);
        float2 c = __half22float2(Z[(long)s2 * 32]);
        float2 d = __half22float2(Z[(long)s3 * 32]);
        if (MODE == 0) {
            float w0 = onorm[s0], w1 = onorm[s1], w2 = onorm[s2], w3 = onorm[s3];
            acc0 = fmaf(w0, a.x, fmaf(w1, b.x, fmaf(w2, c.x, fmaf(w3, d.x, acc0))));
            acc1 = fmaf(w0, a.y, fmaf(w1, b.y, fmaf(w2, c.y, fmaf(w3, d.y, acc1))));
        } else {
            acc0 += (a.x + b.x) + (c.x + d.x);
            acc1 += (a.y + b.y) + (c.y + d.y);
        }
    }
    for (; e < end; e++) {
        int s = csr[e];
        float2 a = __half22float2(Z[(long)s * 32]);
        float w = (MODE == 0) ? onorm[s] : 1.f;
        acc0 = fmaf(w, a.x, acc0);
        acc1 = fmaf(w, a.y, acc1);
    }

    if (MODE == 2) {
        float ni = inorm[v];
        float tv1 = t1[v], tv2 = t2[v];
        float2 uu1 = *reinterpret_cast<const float2*>(u1 + lane * 2);
        float2 uu2 = *reinterpret_cast<const float2*>(u2 + lane * 2);
        float2 bb = *reinterpret_cast<const float2*>(b2 + lane * 2);
        float o0 = ni * acc0 + tv2 * uu2.x + tv1 * uu1.x + bb.x;
        float o1 = ni * acc1 + tv2 * uu2.y + tv1 * uu1.y + bb.y;
        *reinterpret_cast<float2*>(reinterpret_cast<float*>(Hout) + (long)v * 64 + lane * 2) =
            make_float2(o0, o1);
    } else {
        float sc = wprod[v];
        reinterpret_cast<__half2*>(Hout)[(long)v * 32 + lane] =
            __floats2half2_rn(acc0 * sc, acc1 * sc);
    }
}

__global__ void k_ids(const int* __restrict__ ids, float* out, int n) {
    int i = blockIdx.x * blockDim.x + threadIdx.x;
    if (i < n) out[NN * 64 + i] = (float)ids[i];
}

// ---------------- launch ----------------
extern "C" void kernel_launch(void* const* d_in, const int* in_sizes, int n_in,
                              void* d_out, int out_size) {
    const float* h   = (const float*)d_in[0];
    const int*   src = (const int*)d_in[1];
    const int*   dst = (const int*)d_in[2];
    const int*   ids = (const int*)d_in[3];
    const float* W0  = (const float*)d_in[4];
    const float* b0  = (const float*)d_in[5];
    const float* W1  = (const float*)d_in[6];
    const float* b1  = (const float*)d_in[7];
    const float* W2  = (const float*)d_in[8];
    const float* b2  = (const float*)d_in[9];
    float* out = (float*)d_out;
    int E = in_sizes[1];

    __half *pZ1, *pZ2, *pWt;
    float *pon, *pin, *pw, *pt1, *pt2, *pu1, *pu2;
    int *pcin, *pcout, *pptr, *pfill, *pcsr, *ppart;
    cudaGetSymbolAddress((void**)&pZ1, g_Z1);
    cudaGetSymbolAddress((void**)&pZ2, g_Z2);
    cudaGetSymbolAddress((void**)&pWt, g_Wt012);
    cudaGetSymbolAddress((void**)&pu1, g_u1);
    cudaGetSymbolAddress((void**)&pu2, g_u2);
    cudaGetSymbolAddress((void**)&pon, g_onorm);
    cudaGetSymbolAddress((void**)&pin, g_inorm);
    cudaGetSymbolAddress((void**)&pw, g_w);
    cudaGetSymbolAddress((void**)&pt1, g_t1);
    cudaGetSymbolAddress((void**)&pt2, g_t2);
    cudaGetSymbolAddress((void**)&pcin, g_cin);
    cudaGetSymbolAddress((void**)&pcout, g_cout);
    cudaGetSymbolAddress((void**)&pptr, g_ptr);
    cudaGetSymbolAddress((void**)&pfill, g_fill);
    cudaGetSymbolAddress((void**)&pcsr, g_csr);
    cudaGetSymbolAddress((void**)&ppart, g_part);

    static cudaStream_t s2 = nullptr;
    static cudaEvent_t ev_fork = nullptr, ev_csr = nullptr, ev_t = nullptr;
    if (s2 == nullptr) {
        cudaStreamCreateWithFlags(&s2, cudaStreamNonBlocking);
        cudaEventCreateWithFlags(&ev_fork, cudaEventDisableTiming);
        cudaEventCreateWithFlags(&ev_csr, cudaEventDisableTiming);
        cudaEventCreateWithFlags(&ev_t, cudaEventDisableTiming);
    }

    const int gblk = (NN + 127) / 128;
    const int wblk = (NN * 32 + 255) / 256;
    const int nblk = (NN + 255) / 256;
    const int eblk = (E + 255) / 256;

    // ---- fork ----
    cudaEventRecord(ev_fork, 0);
    cudaStreamWaitEvent(s2, ev_fork, 0);

    // s2: CSR prep -> ev_csr; then t1/t2 (overlap gathers 0/1) -> ev_t; ids
    cudaMemsetAsync(pcin, 0, NN * sizeof(int), s2);
    cudaMemsetAsync(pcout, 0, NN * sizeof(int), s2);
    k_degree<<<eblk, 256, 0, s2>>>(src, dst, pcout, pcin, E);
    k_norm_scan<<<NB_SCAN, 256, 0, s2>>>(pcout, pcin, pon, pin, pw, ppart, pptr);
    k_scan_write<<<NB_SCAN, 256, 0, s2>>>(pcin, ppart, pptr, pfill);
    k_fill<<<eblk, 256, 0, s2>>>(src, dst, pfill, pcsr, E);
    cudaEventRecord(ev_csr, s2);
    k_t1<<<nblk, 256, 0, s2>>>(pptr, pcsr, pon, pin, pt1);
    k_t2<<<nblk, 256, 0, s2>>>(pptr, pcsr, pon, pin, pt1, pt2);
    if (out_size > NN * 64) {
        int nid = out_size - NN * 64;
        if (nid > in_sizes[3]) nid = in_sizes[3];
        k_ids<<<(nid + 255) / 256, 256, 0, s2>>>(ids, out, nid);
    }
    cudaEventRecord(ev_t, s2);

    // main: combined weights + single GEMM (no prep dependence)
    k_wcomb<<<1, 256>>>(W0, W1, W2, b0, b1, pWt, pu1, pu2);
    k_gemm0<<<gblk, 128>>>(h, pWt, pZ1);      // X = h @ W012 (unscaled)

    cudaStreamWaitEvent(0, ev_csr, 0);        // need CSR + norms only

    k_gather<0><<<wblk, 256>>>(pZ1, pptr, pcsr, pon, pin, pw, pt1, pt2, pu1, pu2, b2, pZ2);
    k_gather<1><<<wblk, 256>>>(pZ2, pptr, pcsr, pon, pin, pw, pt1, pt2, pu1, pu2, b2, pZ1);

    cudaStreamWaitEvent(0, ev_t, 0);          // t1/t2 ready (computed under gathers 0/1)

    k_gather<2><<<wblk, 256>>>(pZ1, pptr, pcsr, pon, pin, pw, pt1, pt2, pu1, pu2, b2, out);
}

// round 16
// speedup vs baseline: 1.1429x; 1.1192x over previous
#include <cuda_runtime.h>
#include <cuda_fp16.h>
#include <cstdint>

#define NN 100000
#define NE_CAP 1700000
#define NB_SCAN 98   /* ceil(100000/1024) */

// ---- scratch (device globals: allocation-free) ----
__device__ __align__(16) __half g_Hh[NN * 64];   // fp16 hidden activations
__device__ __align__(16) __half g_Z[NN * 64];    // fp16 pre-aggregation buffer
__device__ __align__(16) __half g_Wt0[64 * 128]; // W0^T fp16
__device__ __align__(16) __half g_Wt1[64 * 64];  // W1^T fp16
__device__ __align__(16) __half g_Wt2[64 * 64];  // W2^T fp16
__device__ float g_onorm[NN];
__device__ float g_inorm[NN];
__device__ int   g_deg[2 * NN];                  // [cout | cin], one memset
__device__ int   g_ptr[NN + 1];
__device__ int   g_fill[NN];
__device__ int   g_csr[NE_CAP];
__device__ int   g_part[NB_SCAN];

// ---------------- graph preprocessing (r9-proven) ----------------
__global__ void k_degree(const int* __restrict__ src, const int* __restrict__ dst,
                         int* cout, int* cin, int E) {
    int i = blockIdx.x * blockDim.x + threadIdx.x;
    if (i < E) {
        atomicAdd(&cout[src[i]], 1);
        atomicAdd(&cin[dst[i]], 1);
    }
}

__global__ void k_norm(const int* __restrict__ cout, const int* __restrict__ cin,
                       float* onorm, float* inorm) {
    int i = blockIdx.x * blockDim.x + threadIdx.x;
    if (i < NN) {
        onorm[i] = rsqrtf((float)(cout[i] + 1));   // +1 self loop
        inorm[i] = rsqrtf((float)(cin[i] + 1));
    }
}

__global__ void k_scan_partial(const int* __restrict__ cin, int* part) {
    __shared__ int wsum[8];
    int b = blockIdx.x, t = threadIdx.x;
    int base = b * 1024 + t * 4;
    int s = 0;
#pragma unroll
    for (int j = 0; j < 4; j++) { int i = base + j; if (i < NN) s += cin[i]; }
    for (int o = 16; o > 0; o >>= 1) s += __shfl_down_sync(0xffffffffu, s, o);
    if ((t & 31) == 0) wsum[t >> 5] = s;
    __syncthreads();
    if (t == 0) {
        int tot = 0;
        for (int w = 0; w < 8; w++) tot += wsum[w];
        part[b] = tot;
    }
}

__global__ void k_scan_offsets(int* part, int* ptr) {
    __shared__ int wsum[4];
    int t = threadIdx.x;
    int lane = t & 31, w = t >> 5;
    int v = (t < NB_SCAN) ? part[t] : 0;
    int inc = v;
    for (int o = 1; o < 32; o <<= 1) {
        int u = __shfl_up_sync(0xffffffffu, inc, o);
        if (lane >= o) inc += u;
    }
    if (lane == 31) wsum[w] = inc;
    __syncthreads();
    if (t == 0) {
        int r = 0;
#pragma unroll
        for (int i = 0; i < 4; i++) { int x = wsum[i]; wsum[i] = r; r += x; }
    }
    __syncthreads();
    int excl = wsum[w] + inc - v;
    if (t < NB_SCAN) part[t] = excl;
    if (t == NB_SCAN - 1) ptr[NN] = excl + v;
}

__global__ void k_scan_write(const int* __restrict__ cin, const int* __restrict__ part,
                             int* ptr, int* fill) {
    __shared__ int wexc[8];
    int b = blockIdx.x, t = threadIdx.x;
    int lane = t & 31, warp = t >> 5;
    int base = b * 1024 + t * 4;
    int v[4];
#pragma unroll
    for (int j = 0; j < 4; j++) { int i = base + j; v[j] = (i < NN) ? cin[i] : 0; }
    int s = v[0] + v[1] + v[2] + v[3];
    int inc = s;
    for (int o = 1; o < 32; o <<= 1) {
        int u = __shfl_up_sync(0xffffffffu, inc, o);
        if (lane >= o) inc += u;
    }
    if (lane == 31) wexc[warp] = inc;
    __syncthreads();
    if (warp == 0) {
        int w = (lane < 8) ? wexc[lane] : 0;
        int winc = w;
        for (int o = 1; o < 8; o <<= 1) {
            int u = __shfl_up_sync(0xffffffffu, winc, o);
            if (lane >= o) winc += u;
        }
        if (lane < 8) wexc[lane] = winc - w;
    }
    __syncthreads();
    int pos = part[b] + wexc[warp] + (inc - s);
#pragma unroll
    for (int j = 0; j < 4; j++) {
        int i = base + j;
        if (i < NN) { ptr[i] = pos; fill[i] = pos; }
        pos += v[j];
    }
}

// fill a RANGE of edges [e0, e1) — launched twice, once per stream
__global__ void k_fill(const int* __restrict__ src, const int* __restrict__ dst,
                       int* fill, int* csr, int e0, int e1) {
    int i = e0 + blockIdx.x * blockDim.x + threadIdx.x;
    if (i < e1) {
        int p = atomicAdd(&fill[dst[i]], 1);
        csr[p] = src[i];
    }
}

// ---------------- weight transpose+convert: all three in one launch ----------------
__global__ void k_wt_all(const float* __restrict__ W0, const float* __restrict__ W1,
                         const float* __restrict__ W2,
                         __half* __restrict__ Wt0, __half* __restrict__ Wt1,
                         __half* __restrict__ Wt2) {
    const float* W = (blockIdx.x == 0) ? W0 : (blockIdx.x == 1) ? W1 : W2;
    __half* Wt = (blockIdx.x == 0) ? Wt0 : (blockIdx.x == 1) ? Wt1 : Wt2;
    int K = (blockIdx.x == 0) ? 128 : 64;
    for (int i = threadIdx.x; i < 64 * K; i += blockDim.x) {
        int n = i / K, k = i % K;
        Wt[i] = __float2half(W[k * 64 + n]);
    }
}

// ---------------- tensor-core GEMM: Z = fp16( [onorm .*] (A @ W) ) ----------------
// Block = 128 rows, 4 warps; warp owns cols [16w,16w+16); B frags in registers
// (loaded once), A streamed; k-permutation identical on A/B -> exact.
template <int K, bool SCALE, bool F32A>
__global__ void __launch_bounds__(128) k_gemm_mma(const void* __restrict__ Av,
                                                  const __half* __restrict__ Wt,
                                                  const float* __restrict__ onorm,
                                                  __half* __restrict__ Z) {
    const int tid = threadIdx.x;
    const int warp = tid >> 5, lane = tid & 31;
    const int g = lane >> 2, t = lane & 3;

    uint2 Bf[K / 16][2];
#pragma unroll
    for (int k0 = 0; k0 < K / 16; k0++)
#pragma unroll
        for (int nn = 0; nn < 2; nn++)
            Bf[k0][nn] = *reinterpret_cast<const uint2*>(
                Wt + (long)(warp * 16 + nn * 8 + g) * K + k0 * 16 + 4 * t);

    const int rowblk = blockIdx.x * 128;

#pragma unroll
    for (int m = 0; m < 8; m++) {
        const int r0 = rowblk + m * 16 + g;
        const int r1 = r0 + 8;
        const int r0c = r0 < NN ? r0 : NN - 1;
        const int r1c = r1 < NN ? r1 : NN - 1;

        float acc[2][4];
#pragma unroll
        for (int nn = 0; nn < 2; nn++)
#pragma unroll
            for (int j = 0; j < 4; j++) acc[nn][j] = 0.f;

#pragma unroll
        for (int k0 = 0; k0 < K / 16; k0++) {
            uint2 aA, aB;
            if (F32A) {
                float4 fA = *reinterpret_cast<const float4*>(
                    (const float*)Av + (long)r0c * K + 4 * t + k0 * 16);
                float4 fB = *reinterpret_cast<const float4*>(
                    (const float*)Av + (long)r1c * K + 4 * t + k0 * 16);
                __half2 hA0 = __floats2half2_rn(fA.x, fA.y), hA1 = __floats2half2_rn(fA.z, fA.w);
                __half2 hB0 = __floats2half2_rn(fB.x, fB.y), hB1 = __floats2half2_rn(fB.z, fB.w);
                aA.x = *reinterpret_cast<unsigned int*>(&hA0);
                aA.y = *reinterpret_cast<unsigned int*>(&hA1);
                aB.x = *reinterpret_cast<unsigned int*>(&hB0);
                aB.y = *reinterpret_cast<unsigned int*>(&hB1);
            } else {
                aA = *reinterpret_cast<const uint2*>(
                    (const __half*)Av + (long)r0c * K + 4 * t + k0 * 16);
                aB = *reinterpret_cast<const uint2*>(
                    (const __half*)Av + (long)r1c * K + 4 * t + k0 * 16);
            }
#pragma unroll
            for (int nn = 0; nn < 2; nn++) {
                asm volatile(
                    "mma.sync.aligned.m16n8k16.row.col.f32.f16.f16.f32 "
                    "{%0,%1,%2,%3},{%4,%5,%6,%7},{%8,%9},{%0,%1,%2,%3};"
                    : "+f"(acc[nn][0]), "+f"(acc[nn][1]), "+f"(acc[nn][2]), "+f"(acc[nn][3])
                    : "r"(aA.x), "r"(aB.x), "r"(aA.y), "r"(aB.y),
                      "r"(Bf[k0][nn].x), "r"(Bf[k0][nn].y));
            }
        }

        float s0 = 1.f, s1 = 1.f;
        if (SCALE) { s0 = onorm[r0c]; s1 = onorm[r1c]; }
#pragma unroll
        for (int nn = 0; nn < 2; nn++) {
            int col = warp * 16 + nn * 8 + 2 * t;
            if (r0 < NN)
                *reinterpret_cast<__half2*>(Z + (long)r0 * 64 + col) =
                    __floats2half2_rn(acc[nn][0] * s0, acc[nn][1] * s0);
            if (r1 < NN)
                *reinterpret_cast<__half2*>(Z + (long)r1 * 64 + col) =
                    __floats2half2_rn(acc[nn][2] * s1, acc[nn][3] * s1);
        }
    }
}

// ---------------- SpMM gather (r9-proven) ----------------
// ONORM: apply onorm[s] per source row (layer 0, where GEMM ran unscaled).
template <bool HALF_OUT, bool ONORM>
__global__ void __launch_bounds__(256) k_gather(const __half* __restrict__ Zh,
                                                const int* __restrict__ ptr,
                                                const int* __restrict__ csr,
                                                const float* __restrict__ onorm,
                                                const float* __restrict__ inorm,
                                                const float* __restrict__ bias,
                                                void* __restrict__ Hout) {
    int v = (blockIdx.x * blockDim.x + threadIdx.x) >> 5;
    int lane = threadIdx.x & 31;
    if (v >= NN) return;
    const __half2* Z = reinterpret_cast<const __half2*>(Zh) + lane;  // row stride 32

    int beg = ptr[v], end = ptr[v + 1];
    float2 f0 = __half22float2(Z[(long)v * 32]);
    float selfw = ONORM ? onorm[v] : 1.f;
    float acc0 = f0.x * selfw, acc1 = f0.y * selfw;

    int e = beg;
    for (; e + 4 <= end; e += 4) {
        int s0 = csr[e], s1 = csr[e + 1], s2 = csr[e + 2], s3 = csr[e + 3];
        float2 a = __half22float2(Z[(long)s0 * 32]);
        float2 b = __half22float2(Z[(long)s1 * 32]);
        float2 c = __half22float2(Z[(long)s2 * 32]);
        float2 d = __half22float2(Z[(long)s3 * 32]);
        if (ONORM) {
            float w0 = onorm[s0], w1 = onorm[s1], w2 = onorm[s2], w3 = onorm[s3];
            acc0 = fmaf(w0, a.x, fmaf(w1, b.x, fmaf(w2, c.x, fmaf(w3, d.x, acc0))));
            acc1 = fmaf(w0, a.y, fmaf(w1, b.y, fmaf(w2, c.y, fmaf(w3, d.y, acc1))));
        } else {
            acc0 += (a.x + b.x) + (c.x + d.x);
            acc1 += (a.y + b.y) + (c.y + d.y);
        }
    }
    for (; e < end; e++) {
        int s = csr[e];
        float2 a = __half22float2(Z[(long)s * 32]);
        float w = ONORM ? onorm[s] : 1.f;
        acc0 = fmaf(w, a.x, acc0);
        acc1 = fmaf(w, a.y, acc1);
    }

    float ni = inorm[v];
    float2 bb = *reinterpret_cast<const float2*>(bias + lane * 2);
    float o0 = ni * acc0 + bb.x;
    float o1 = ni * acc1 + bb.y;
    if (HALF_OUT) {
        reinterpret_cast<__half2*>(Hout)[(long)v * 32 + lane] = __floats2half2_rn(o0, o1);
    } else {
        *reinterpret_cast<float2*>(reinterpret_cast<float*>(Hout) + (long)v * 64 + lane * 2) =
            make_float2(o0, o1);
    }
}

__global__ void k_ids(const int* __restrict__ ids, float* out, int n) {
    int i = blockIdx.x * blockDim.x + threadIdx.x;
    if (i < n) out[NN * 64 + i] = (float)ids[i];
}

// ---------------- launch ----------------
extern "C" void kernel_launch(void* const* d_in, const int* in_sizes, int n_in,
                              void* d_out, int out_size) {
    const float* h   = (const float*)d_in[0];
    const int*   src = (const int*)d_in[1];
    const int*   dst = (const int*)d_in[2];
    const int*   ids = (const int*)d_in[3];
    const float* W0  = (const float*)d_in[4];
    const float* b0  = (const float*)d_in[5];
    const float* W1  = (const float*)d_in[6];
    const float* b1  = (const float*)d_in[7];
    const float* W2  = (const float*)d_in[8];
    const float* b2  = (const float*)d_in[9];
    float* out = (float*)d_out;
    int E = in_sizes[1];

    __half *pHh, *pZ, *pWt0, *pWt1, *pWt2;
    float *pon, *pin;
    int *pdeg, *pptr, *pfill, *pcsr, *ppart;
    cudaGetSymbolAddress((void**)&pHh, g_Hh);
    cudaGetSymbolAddress((void**)&pZ, g_Z);
    cudaGetSymbolAddress((void**)&pWt0, g_Wt0);
    cudaGetSymbolAddress((void**)&pWt1, g_Wt1);
    cudaGetSymbolAddress((void**)&pWt2, g_Wt2);
    cudaGetSymbolAddress((void**)&pon, g_onorm);
    cudaGetSymbolAddress((void**)&pin, g_inorm);
    cudaGetSymbolAddress((void**)&pdeg, g_deg);
    cudaGetSymbolAddress((void**)&pptr, g_ptr);
    cudaGetSymbolAddress((void**)&pfill, g_fill);
    cudaGetSymbolAddress((void**)&pcsr, g_csr);
    cudaGetSymbolAddress((void**)&ppart, g_part);
    int* pcout = pdeg;
    int* pcin  = pdeg + NN;

    static cudaStream_t s2 = nullptr;
    static cudaEvent_t ev_fork = nullptr, ev_scanw = nullptr, ev_join = nullptr;
    if (s2 == nullptr) {
        cudaStreamCreateWithFlags(&s2, cudaStreamNonBlocking);
        cudaEventCreateWithFlags(&ev_fork, cudaEventDisableTiming);
        cudaEventCreateWithFlags(&ev_scanw, cudaEventDisableTiming);
        cudaEventCreateWithFlags(&ev_join, cudaEventDisableTiming);
    }

    const int gblk = (NN + 127) / 128;          // 128 rows/block kernels
    const int wblk = (NN * 32 + 255) / 256;     // warp-per-node kernels

    const int Ehalf = E / 2;

    // ---- fork: prep chain on s2; weights + GEMM0 on main ----
    cudaEventRecord(ev_fork, 0);
    cudaStreamWaitEvent(s2, ev_fork, 0);

    cudaMemsetAsync(pdeg, 0, 2 * NN * sizeof(int), s2);
    k_degree<<<(E + 255) / 256, 256, 0, s2>>>(src, dst, pcout, pcin, E);
    k_norm<<<(NN + 255) / 256, 256, 0, s2>>>(pcout, pcin, pon, pin);
    k_scan_partial<<<NB_SCAN, 256, 0, s2>>>(pcin, ppart);
    k_scan_offsets<<<1, 128, 0, s2>>>(ppart, pptr);
    k_scan_write<<<NB_SCAN, 256, 0, s2>>>(pcin, ppart, pptr, pfill);
    cudaEventRecord(ev_scanw, s2);
    // s2 fills the FIRST half of the edges
    k_fill<<<(Ehalf + 255) / 256, 256, 0, s2>>>(src, dst, pfill, pcsr, 0, Ehalf);
    if (out_size > NN * 64) {
        int nid = out_size - NN * 64;
        if (nid > in_sizes[3]) nid = in_sizes[3];
        k_ids<<<(nid + 255) / 256, 256, 0, s2>>>(ids, out, nid);
    }
    cudaEventRecord(ev_join, s2);

    // main: weights + unscaled GEMM0 (no prep dependence)
    k_wt_all<<<3, 256>>>(W0, W1, W2, pWt0, pWt1, pWt2);
    k_gemm_mma<128, false, true><<<gblk, 128>>>(h, pWt0, pon, pZ);

    // main fills the SECOND half of the edges, concurrent with s2's first half
    cudaStreamWaitEvent(0, ev_scanw, 0);
    k_fill<<<(E - Ehalf + 255) / 256, 256>>>(src, dst, pfill, pcsr, Ehalf, E);

    cudaStreamWaitEvent(0, ev_join, 0);   // s2's half + ids done

    // ---- layer chain (gather0 applies onorm per source row) ----
    k_gather<true, true><<<wblk, 256>>>(pZ, pptr, pcsr, pon, pin, b0, pHh);
    k_gemm_mma<64, true, false><<<gblk, 128>>>(pHh, pWt1, pon, pZ);
    k_gather<true, false><<<wblk, 256>>>(pZ, pptr, pcsr, pon, pin, b1, pHh);
    k_gemm_mma<64, true, false><<<gblk, 128>>>(pHh, pWt2, pon, pZ);
    k_gather<false, false><<<wblk, 256>>>(pZ, pptr, pcsr, pon, pin, b2, out);
}

// round 17
// speedup vs baseline: 1.1706x; 1.0242x over previous
#include <cuda_runtime.h>
#include <cuda_fp16.h>
#include <cstdint>

#define NN 100000
#define NE_CAP 1700000
#define NB_SCAN 98   /* ceil(100000/1024) */

// ---- scratch (device globals: allocation-free) ----
__device__ __align__(16) __half g_Z1[NN * 64];
__device__ __align__(16) __half g_Z2[NN * 64];
__device__ __align__(16) __half g_Wt0[64 * 128]; // W0^T fp16
__device__ __align__(16) __half g_Wt1[64 * 64];  // W1^T fp16
__device__ __align__(16) __half g_Wt2[64 * 64];  // W2^T fp16
__device__ float g_onorm[NN];
__device__ float g_inorm[NN];
__device__ int   g_deg[2 * NN];                  // [cout | cin], one memset
__device__ int   g_ptr[NN + 1];
__device__ int   g_fill[NN];
__device__ int   g_csr[NE_CAP];
__device__ int   g_part[NB_SCAN];

// ---------------- graph preprocessing (r9-proven) ----------------
__global__ void k_degree(const int* __restrict__ src, const int* __restrict__ dst,
                         int* cout, int* cin, int E) {
    int i = blockIdx.x * blockDim.x + threadIdx.x;
    if (i < E) {
        atomicAdd(&cout[src[i]], 1);
        atomicAdd(&cin[dst[i]], 1);
    }
}

__global__ void k_norm(const int* __restrict__ cout, const int* __restrict__ cin,
                       float* onorm, float* inorm) {
    int i = blockIdx.x * blockDim.x + threadIdx.x;
    if (i < NN) {
        onorm[i] = rsqrtf((float)(cout[i] + 1));   // +1 self loop
        inorm[i] = rsqrtf((float)(cin[i] + 1));
    }
}

__global__ void k_scan_partial(const int* __restrict__ cin, int* part) {
    __shared__ int wsum[8];
    int b = blockIdx.x, t = threadIdx.x;
    int base = b * 1024 + t * 4;
    int s = 0;
#pragma unroll
    for (int j = 0; j < 4; j++) { int i = base + j; if (i < NN) s += cin[i]; }
    for (int o = 16; o > 0; o >>= 1) s += __shfl_down_sync(0xffffffffu, s, o);
    if ((t & 31) == 0) wsum[t >> 5] = s;
    __syncthreads();
    if (t == 0) {
        int tot = 0;
        for (int w = 0; w < 8; w++) tot += wsum[w];
        part[b] = tot;
    }
}

__global__ void k_scan_offsets(int* part, int* ptr) {
    __shared__ int wsum[4];
    int t = threadIdx.x;
    int lane = t & 31, w = t >> 5;
    int v = (t < NB_SCAN) ? part[t] : 0;
    int inc = v;
    for (int o = 1; o < 32; o <<= 1) {
        int u = __shfl_up_sync(0xffffffffu, inc, o);
        if (lane >= o) inc += u;
    }
    if (lane == 31) wsum[w] = inc;
    __syncthreads();
    if (t == 0) {
        int r = 0;
#pragma unroll
        for (int i = 0; i < 4; i++) { int x = wsum[i]; wsum[i] = r; r += x; }
    }
    __syncthreads();
    int excl = wsum[w] + inc - v;
    if (t < NB_SCAN) part[t] = excl;
    if (t == NB_SCAN - 1) ptr[NN] = excl + v;
}

__global__ void k_scan_write(const int* __restrict__ cin, const int* __restrict__ part,
                             int* ptr, int* fill) {
    __shared__ int wexc[8];
    int b = blockIdx.x, t = threadIdx.x;
    int lane = t & 31, warp = t >> 5;
    int base = b * 1024 + t * 4;
    int v[4];
#pragma unroll
    for (int j = 0; j < 4; j++) { int i = base + j; v[j] = (i < NN) ? cin[i] : 0; }
    int s = v[0] + v[1] + v[2] + v[3];
    int inc = s;
    for (int o = 1; o < 32; o <<= 1) {
        int u = __shfl_up_sync(0xffffffffu, inc, o);
        if (lane >= o) inc += u;
    }
    if (lane == 31) wexc[warp] = inc;
    __syncthreads();
    if (warp == 0) {
        int w = (lane < 8) ? wexc[lane] : 0;
        int winc = w;
        for (int o = 1; o < 8; o <<= 1) {
            int u = __shfl_up_sync(0xffffffffu, winc, o);
            if (lane >= o) winc += u;
        }
        if (lane < 8) wexc[lane] = winc - w;
    }
    __syncthreads();
    int pos = part[b] + wexc[warp] + (inc - s);
#pragma unroll
    for (int j = 0; j < 4; j++) {
        int i = base + j;
        if (i < NN) { ptr[i] = pos; fill[i] = pos; }
        pos += v[j];
    }
}

__global__ void k_fill(const int* __restrict__ src, const int* __restrict__ dst,
                       int* fill, int* csr, int E) {
    int i = blockIdx.x * blockDim.x + threadIdx.x;
    if (i < E) {
        int p = atomicAdd(&fill[dst[i]], 1);
        csr[p] = src[i];
    }
}

// ---------------- weight transpose+convert ----------------
__global__ void k_wt_all(const float* __restrict__ W0, const float* __restrict__ W1,
                         const float* __restrict__ W2,
                         __half* __restrict__ Wt0, __half* __restrict__ Wt1,
                         __half* __restrict__ Wt2) {
    const float* W = (blockIdx.x == 0) ? W0 : (blockIdx.x == 1) ? W1 : W2;
    __half* Wt = (blockIdx.x == 0) ? Wt0 : (blockIdx.x == 1) ? Wt1 : Wt2;
    int K = (blockIdx.x == 0) ? 128 : 64;
    for (int i = threadIdx.x; i < 64 * K; i += blockDim.x) {
        int n = i / K, k = i % K;
        Wt[i] = __float2half(W[k * 64 + n]);
    }
}

// ---------------- GEMM0: Z = fp16(h fp32 @ W0), B-in-registers, unscaled ----------------
__global__ void __launch_bounds__(128) k_gemm0(const float* __restrict__ A,
                                               const __half* __restrict__ Wt,
                                               __half* __restrict__ Z) {
    const int K = 128;
    const int tid = threadIdx.x;
    const int warp = tid >> 5, lane = tid & 31;
    const int g = lane >> 2, t = lane & 3;

    uint2 Bf[8][2];
#pragma unroll
    for (int k0 = 0; k0 < 8; k0++)
#pragma unroll
        for (int nn = 0; nn < 2; nn++)
            Bf[k0][nn] = *reinterpret_cast<const uint2*>(
                Wt + (long)(warp * 16 + nn * 8 + g) * K + k0 * 16 + 4 * t);

    const int rowblk = blockIdx.x * 128;

#pragma unroll
    for (int m = 0; m < 8; m++) {
        const int r0 = rowblk + m * 16 + g;
        const int r1 = r0 + 8;
        const int r0c = r0 < NN ? r0 : NN - 1;
        const int r1c = r1 < NN ? r1 : NN - 1;

        float acc[2][4];
#pragma unroll
        for (int nn = 0; nn < 2; nn++)
#pragma unroll
            for (int j = 0; j < 4; j++) acc[nn][j] = 0.f;

#pragma unroll
        for (int k0 = 0; k0 < 8; k0++) {
            float4 fA = *reinterpret_cast<const float4*>(A + (long)r0c * K + 4 * t + k0 * 16);
            float4 fB = *reinterpret_cast<const float4*>(A + (long)r1c * K + 4 * t + k0 * 16);
            __half2 hA0 = __floats2half2_rn(fA.x, fA.y), hA1 = __floats2half2_rn(fA.z, fA.w);
            __half2 hB0 = __floats2half2_rn(fB.x, fB.y), hB1 = __floats2half2_rn(fB.z, fB.w);
            uint2 aA, aB;
            aA.x = *reinterpret_cast<unsigned int*>(&hA0);
            aA.y = *reinterpret_cast<unsigned int*>(&hA1);
            aB.x = *reinterpret_cast<unsigned int*>(&hB0);
            aB.y = *reinterpret_cast<unsigned int*>(&hB1);
#pragma unroll
            for (int nn = 0; nn < 2; nn++) {
                asm volatile(
                    "mma.sync.aligned.m16n8k16.row.col.f32.f16.f16.f32 "
                    "{%0,%1,%2,%3},{%4,%5,%6,%7},{%8,%9},{%0,%1,%2,%3};"
                    : "+f"(acc[nn][0]), "+f"(acc[nn][1]), "+f"(acc[nn][2]), "+f"(acc[nn][3])
                    : "r"(aA.x), "r"(aB.x), "r"(aA.y), "r"(aB.y),
                      "r"(Bf[k0][nn].x), "r"(Bf[k0][nn].y));
            }
        }
#pragma unroll
        for (int nn = 0; nn < 2; nn++) {
            int col = warp * 16 + nn * 8 + 2 * t;
            if (r0 < NN)
                *reinterpret_cast<__half2*>(Z + (long)r0 * 64 + col) =
                    __floats2half2_rn(acc[nn][0], acc[nn][1]);
            if (r1 < NN)
                *reinterpret_cast<__half2*>(Z + (long)r1 * 64 + col) =
                    __floats2half2_rn(acc[nn][2], acc[nn][3]);
        }
    }
}

// ---------------- FUSED gather + GEMM (warp-per-node preserved) ----------------
// Block = 256 threads = 8 warps = 8 NODES (same gather shape as r9).
// Phase 1: warp w gathers node base+w (r9 inner loop), H row (fp16) -> smem.
// Phase 2: warp w computes output cols [8w,8w+8) for all 8 rows:
//   4x m16n8k16 MMAs, A rows 8-15 zeroed (only 8 real rows), B frags from L1.
// Zout[row] = onorm[row] * (H[row] @ W).
// ONORM_EDGE: weight gathered rows by onorm[src] (layer 1 only, Z0 unscaled).
template <bool ONORM_EDGE>
__global__ void __launch_bounds__(256) k_gather_gemm(const __half* __restrict__ Zin,
                                                     const int* __restrict__ ptr,
                                                     const int* __restrict__ csr,
                                                     const float* __restrict__ onorm,
                                                     const float* __restrict__ inorm,
                                                     const float* __restrict__ bias,
                                                     const __half* __restrict__ Wt,
                                                     __half* __restrict__ Zout) {
    __shared__ unsigned int Hs[8 * 36];   // 8 rows x 32 half2 (stride 36 words)
    const int tid = threadIdx.x;
    const int warp = tid >> 5, lane = tid & 31;
    const int base = blockIdx.x * 8;
    const int v = base + warp;
    const __half2* Z = reinterpret_cast<const __half2*>(Zin) + lane;  // row stride 32

    // ---- phase 1: gather (identical to r9's k_gather inner loop) ----
    {
        float o0 = 0.f, o1 = 0.f;
        if (v < NN) {
            int beg = ptr[v], end = ptr[v + 1];
            float2 f0 = __half22float2(Z[(long)v * 32]);
            float selfw = ONORM_EDGE ? onorm[v] : 1.f;
            float acc0 = f0.x * selfw, acc1 = f0.y * selfw;
            int e = beg;
            for (; e + 4 <= end; e += 4) {
                int s0 = csr[e], s1 = csr[e + 1], s2 = csr[e + 2], s3 = csr[e + 3];
                float2 a = __half22float2(Z[(long)s0 * 32]);
                float2 b = __half22float2(Z[(long)s1 * 32]);
                float2 c = __half22float2(Z[(long)s2 * 32]);
                float2 d = __half22float2(Z[(long)s3 * 32]);
                if (ONORM_EDGE) {
                    float w0 = onorm[s0], w1 = onorm[s1], w2 = onorm[s2], w3 = onorm[s3];
                    acc0 = fmaf(w0, a.x, fmaf(w1, b.x, fmaf(w2, c.x, fmaf(w3, d.x, acc0))));
                    acc1 = fmaf(w0, a.y, fmaf(w1, b.y, fmaf(w2, c.y, fmaf(w3, d.y, acc1))));
                } else {
                    acc0 += (a.x + b.x) + (c.x + d.x);
                    acc1 += (a.y + b.y) + (c.y + d.y);
                }
            }
            for (; e < end; e++) {
                int s = csr[e];
                float2 a = __half22float2(Z[(long)s * 32]);
                float w = ONORM_EDGE ? onorm[s] : 1.f;
                acc0 = fmaf(w, a.x, acc0);
                acc1 = fmaf(w, a.y, acc1);
            }
            float ni = inorm[v];
            float2 bb = *reinterpret_cast<const float2*>(bias + lane * 2);
            o0 = ni * acc0 + bb.x;
            o1 = ni * acc1 + bb.y;
        }
        __half2 hv = __floats2half2_rn(o0, o1);
        Hs[warp * 36 + lane] = *reinterpret_cast<unsigned int*>(&hv);
    }
    __syncthreads();

    // ---- phase 2: GEMM (K=64). Warp w -> cols [8w, 8w+8), rows 0-7 real. ----
    const int g = lane >> 2, t = lane & 3;
    uint2 Bf[4];
#pragma unroll
    for (int k0 = 0; k0 < 4; k0++)
        Bf[k0] = *reinterpret_cast<const uint2*>(
            Wt + (long)(warp * 8 + g) * 64 + k0 * 16 + 4 * t);

    float acc[4] = {0.f, 0.f, 0.f, 0.f};
#pragma unroll
    for (int k0 = 0; k0 < 4; k0++) {
        uint2 aA = *reinterpret_cast<const uint2*>(&Hs[g * 36 + k0 * 8 + 2 * t]);
        asm volatile(
            "mma.sync.aligned.m16n8k16.row.col.f32.f16.f16.f32 "
            "{%0,%1,%2,%3},{%4,%5,%6,%7},{%8,%9},{%0,%1,%2,%3};"
            : "+f"(acc[0]), "+f"(acc[1]), "+f"(acc[2]), "+f"(acc[3])
            : "r"(aA.x), "r"(0u), "r"(aA.y), "r"(0u),
              "r"(Bf[k0].x), "r"(Bf[k0].y));
    }

    int row = base + g;                 // rows 0-7 of this block
    if (row < NN) {
        float s = onorm[row];
        int col = warp * 8 + 2 * t;
        *reinterpret_cast<__half2*>(Zout + (long)row * 64 + col) =
            __floats2half2_rn(acc[0] * s, acc[1] * s);
    }
}

// ---------------- final gather (fp32 out, r9-proven) ----------------
__global__ void __launch_bounds__(256) k_gather_f(const __half* __restrict__ Zh,
                                                  const int* __restrict__ ptr,
                                                  const int* __restrict__ csr,
                                                  const float* __restrict__ inorm,
                                                  const float* __restrict__ bias,
                                                  float* __restrict__ Hout) {
    int v = (blockIdx.x * blockDim.x + threadIdx.x) >> 5;
    int lane = threadIdx.x & 31;
    if (v >= NN) return;
    const __half2* Z = reinterpret_cast<const __half2*>(Zh) + lane;

    int beg = ptr[v], end = ptr[v + 1];
    float2 f0 = __half22float2(Z[(long)v * 32]);
    float acc0 = f0.x, acc1 = f0.y;

    int e = beg;
    for (; e + 4 <= end; e += 4) {
        int s0 = csr[e], s1 = csr[e + 1], s2 = csr[e + 2], s3 = csr[e + 3];
        float2 a = __half22float2(Z[(long)s0 * 32]);
        float2 b = __half22float2(Z[(long)s1 * 32]);
        float2 c = __half22float2(Z[(long)s2 * 32]);
        float2 d = __half22float2(Z[(long)s3 * 32]);
        acc0 += (a.x + b.x) + (c.x + d.x);
        acc1 += (a.y + b.y) + (c.y + d.y);
    }
    for (; e < end; e++) {
        int s = csr[e];
        float2 a = __half22float2(Z[(long)s * 32]);
        acc0 += a.x;
        acc1 += a.y;
    }

    float ni = inorm[v];
    float2 bb = *reinterpret_cast<const float2*>(bias + lane * 2);
    *reinterpret_cast<float2*>(Hout + (long)v * 64 + lane * 2) =
        make_float2(ni * acc0 + bb.x, ni * acc1 + bb.y);
}

__global__ void k_ids(const int* __restrict__ ids, float* out, int n) {
    int i = blockIdx.x * blockDim.x + threadIdx.x;
    if (i < n) out[NN * 64 + i] = (float)ids[i];
}

// ---------------- launch ----------------
extern "C" void kernel_launch(void* const* d_in, const int* in_sizes, int n_in,
                              void* d_out, int out_size) {
    const float* h   = (const float*)d_in[0];
    const int*   src = (const int*)d_in[1];
    const int*   dst = (const int*)d_in[2];
    const int*   ids = (const int*)d_in[3];
    const float* W0  = (const float*)d_in[4];
    const float* b0  = (const float*)d_in[5];
    const float* W1  = (const float*)d_in[6];
    const float* b1  = (const float*)d_in[7];
    const float* W2  = (const float*)d_in[8];
    const float* b2  = (const float*)d_in[9];
    float* out = (float*)d_out;
    int E = in_sizes[1];

    __half *pZ1, *pZ2, *pWt0, *pWt1, *pWt2;
    float *pon, *pin;
    int *pdeg, *pptr, *pfill, *pcsr, *ppart;
    cudaGetSymbolAddress((void**)&pZ1, g_Z1);
    cudaGetSymbolAddress((void**)&pZ2, g_Z2);
    cudaGetSymbolAddress((void**)&pWt0, g_Wt0);
    cudaGetSymbolAddress((void**)&pWt1, g_Wt1);
    cudaGetSymbolAddress((void**)&pWt2, g_Wt2);
    cudaGetSymbolAddress((void**)&pon, g_onorm);
    cudaGetSymbolAddress((void**)&pin, g_inorm);
    cudaGetSymbolAddress((void**)&pdeg, g_deg);
    cudaGetSymbolAddress((void**)&pptr, g_ptr);
    cudaGetSymbolAddress((void**)&pfill, g_fill);
    cudaGetSymbolAddress((void**)&pcsr, g_csr);
    cudaGetSymbolAddress((void**)&ppart, g_part);
    int* pcout = pdeg;
    int* pcin  = pdeg + NN;

    static cudaStream_t s2 = nullptr;
    static cudaEvent_t ev_fork = nullptr, ev_join = nullptr;
    if (s2 == nullptr) {
        cudaStreamCreateWithFlags(&s2, cudaStreamNonBlocking);
        cudaEventCreateWithFlags(&ev_fork, cudaEventDisableTiming);
        cudaEventCreateWithFlags(&ev_join, cudaEventDisableTiming);
    }

    const int gblk = (NN + 127) / 128;
    const int wblk = (NN * 32 + 255) / 256;   // warp-per-node kernels
    const int fblk = (NN + 7) / 8;            // fused gather+gemm: 8 nodes/block

    // ---- fork: prep chain on s2; weights + GEMM0 on main (r9 schedule) ----
    cudaEventRecord(ev_fork, 0);
    cudaStreamWaitEvent(s2, ev_fork, 0);

    cudaMemsetAsync(pdeg, 0, 2 * NN * sizeof(int), s2);
    k_degree<<<(E + 255) / 256, 256, 0, s2>>>(src, dst, pcout, pcin, E);
    k_norm<<<(NN + 255) / 256, 256, 0, s2>>>(pcout, pcin, pon, pin);
    k_scan_partial<<<NB_SCAN, 256, 0, s2>>>(pcin, ppart);
    k_scan_offsets<<<1, 128, 0, s2>>>(ppart, pptr);
    k_scan_write<<<NB_SCAN, 256, 0, s2>>>(pcin, ppart, pptr, pfill);
    k_fill<<<(E + 255) / 256, 256, 0, s2>>>(src, dst, pfill, pcsr, E);
    if (out_size > NN * 64) {
        int nid = out_size - NN * 64;
        if (nid > in_sizes[3]) nid = in_sizes[3];
        k_ids<<<(nid + 255) / 256, 256, 0, s2>>>(ids, out, nid);
    }
    cudaEventRecord(ev_join, s2);

    k_wt_all<<<3, 256>>>(W0, W1, W2, pWt0, pWt1, pWt2);
    k_gemm0<<<gblk, 128>>>(h, pWt0, pZ1);     // Z0 unscaled (no prep dependence)

    cudaStreamWaitEvent(0, ev_join, 0);       // join: CSR + norms ready

    // ---- fused layer chain: 3 kernels total ----
    k_gather_gemm<true><<<fblk, 256>>>(pZ1, pptr, pcsr, pon, pin, b0, pWt1, pZ2);
    k_gather_gemm<false><<<fblk, 256>>>(pZ2, pptr, pcsr, pon, pin, b1, pWt2, pZ1);
    k_gather_f<<<wblk, 256>>>(pZ1, pptr, pcsr, pin, b2, out);
}